// round 2
// baseline (speedup 1.0000x reference)
#include <cuda_runtime.h>
#include <math.h>

// ===================== problem constants =====================
namespace {
constexpr int Bz  = 8;
constexpr int S   = 2048;
constexpr int D   = 128;
constexpr int DV  = 128;
constexpr int CHUNKS = 16;             // k-chunks per batch
constexpr int CROWS  = S / CHUNKS;     // 128 rows per chunk
constexpr int KT     = 8;              // rows staged per iteration
constexpr int NST1   = CROWS / KT;     // 16 stages
constexpr unsigned FLAG_READY = 32u;
}

// Scratch: per-chunk partials of K^T V, reduced M, and sync counters.
__device__ float    g_Mp[Bz * CHUNKS * D * DV];   // 8 MB
__device__ float    g_M [Bz * D * DV];            // 512 KB
__device__ unsigned g_cnt [Bz];                   // zero-init; self-resetting
__device__ unsigned g_done[Bz];                   // zero-init; self-resetting

// ===================== packed f32x2 helpers =====================
__device__ __forceinline__ unsigned long long pk2(float lo, float hi) {
    unsigned long long r;
    asm("mov.b64 %0, {%1, %2};" : "=l"(r) : "f"(lo), "f"(hi));
    return r;
}
__device__ __forceinline__ void fma2(unsigned long long& d,
                                     unsigned long long a,
                                     unsigned long long b) {
    asm("fma.rn.f32x2 %0, %1, %2, %0;" : "+l"(d) : "l"(a), "l"(b));
}
__device__ __forceinline__ float2 unpk2(unsigned long long v) {
    float lo, hi;
    asm("mov.b64 {%0, %1}, %2;" : "=f"(lo), "=f"(hi) : "l"(v));
    return make_float2(lo, hi);
}

// ===================== fused kernel =====================
// grid = Bz*CHUNKS = 128 blocks (all co-resident on 148 SMs), 256 threads.
// Phase 1: block (b,c) computes partial K^T V for its 128-row chunk -> g_Mp.
//          Last finisher per batch reduces 16 partials -> g_M, raises flag.
// Phase 2: all 16 blocks of batch b load M into smem, compute their Q-tile.
__global__ void __launch_bounds__(256, 1)
fused_attn_kernel(const float* __restrict__ Qp, const float* __restrict__ Kp,
                  const float* __restrict__ Vp, const float* __restrict__ sfp,
                  float* __restrict__ Op) {
    extern __shared__ float sh[];
    // phase-1 aliases
    float* Ks = sh;                 // [2][KT][D]   = 2048 floats
    float* Vs = sh + 2 * KT * D;    // [2][KT][DV]  = 2048 floats
    // phase-2 aliases (reuse same smem)
    float* Ms = sh;                 // [D][DV]      = 16384 floats
    float* Qs = sh + D * DV;        // [2][8][128]  = 2048 floats

    const int b   = blockIdx.x >> 4;
    const int c   = blockIdx.x & 15;
    const int tid = threadIdx.x;
    const int ty  = tid >> 3;       // 0..31 -> rows [ty*4, ty*4+4)
    const int tx  = tid & 7;        // 0..7  -> cols [tx*16, tx*16+16)

    // ---------------- phase 1: partial K^T V ----------------
    {
        const float* Kb = Kp + ((size_t)(b * S + c * CROWS)) * D;
        const float* Vb = Vp + ((size_t)(b * S + c * CROWS)) * DV;
        const int lrow = tid >> 5;          // 0..7
        const int lcol = (tid & 31) * 4;    // 0..124

        unsigned long long acc[4][8];
#pragma unroll
        for (int i = 0; i < 4; ++i)
#pragma unroll
            for (int j = 0; j < 8; ++j) acc[i][j] = 0ull;

        // prologue stage 0
        *(float4*)&Ks[(0 * KT + lrow) * D + lcol] =
            *(const float4*)(Kb + lrow * D + lcol);
        *(float4*)&Vs[(0 * KT + lrow) * DV + lcol] =
            *(const float4*)(Vb + lrow * DV + lcol);
        __syncthreads();

        for (int s = 0; s < NST1; ++s) {
            const int cur = s & 1;
            float4 knext, vnext;
            const bool more = (s + 1 < NST1);
            if (more) {
                knext = *(const float4*)(Kb + ((s + 1) * KT + lrow) * D + lcol);
                vnext = *(const float4*)(Vb + ((s + 1) * KT + lrow) * DV + lcol);
            }
#pragma unroll
            for (int r = 0; r < KT; ++r) {
                const float* krow = &Ks[(cur * KT + r) * D];
                const float* vrow = &Vs[(cur * KT + r) * DV];
                float4 k4 = *(const float4*)&krow[ty * 4];
                float4 v0 = *(const float4*)&vrow[tx * 16 + 0];
                float4 v1 = *(const float4*)&vrow[tx * 16 + 4];
                float4 v2f = *(const float4*)&vrow[tx * 16 + 8];
                float4 v3 = *(const float4*)&vrow[tx * 16 + 12];
                unsigned long long v2[8] = {
                    pk2(v0.x, v0.y),  pk2(v0.z, v0.w),
                    pk2(v1.x, v1.y),  pk2(v1.z, v1.w),
                    pk2(v2f.x, v2f.y), pk2(v2f.z, v2f.w),
                    pk2(v3.x, v3.y),  pk2(v3.z, v3.w) };
                float kk[4] = {k4.x, k4.y, k4.z, k4.w};
#pragma unroll
                for (int i = 0; i < 4; ++i) {
                    unsigned long long kd = pk2(kk[i], kk[i]);
#pragma unroll
                    for (int j = 0; j < 8; ++j) fma2(acc[i][j], kd, v2[j]);
                }
            }
            if (more) {
                const int nxt = cur ^ 1;
                *(float4*)&Ks[(nxt * KT + lrow) * D + lcol] = knext;
                *(float4*)&Vs[(nxt * KT + lrow) * DV + lcol] = vnext;
            }
            __syncthreads();
        }

        // write partial tile (plain coalesced-ish STG.128)
        float* Pp = g_Mp + ((size_t)(b * CHUNKS + c)) * D * DV;
#pragma unroll
        for (int i = 0; i < 4; ++i) {
            const int row = ty * 4 + i;
#pragma unroll
            for (int j2 = 0; j2 < 4; ++j2) {
                float2 a = unpk2(acc[i][2 * j2]);
                float2 b2 = unpk2(acc[i][2 * j2 + 1]);
                float4 w = make_float4(a.x, a.y, b2.x, b2.y);
                *(float4*)&Pp[row * DV + tx * 16 + j2 * 4] = w;
            }
        }
    }
    __threadfence();

    __shared__ unsigned sh_my;
    if (tid == 0) sh_my = atomicAdd(&g_cnt[b], 1u);
    __syncthreads();
    const bool is_reducer = (sh_my == CHUNKS - 1);

    // ---------------- reduce + handshake ----------------
    if (is_reducer) {
        __threadfence();  // see all producers' partials
        const float* base = g_Mp + (size_t)b * CHUNKS * D * DV;
        float* Mb = g_M + (size_t)b * D * DV;
#pragma unroll 1
        for (int k = 0; k < 16; ++k) {
            const int idx4 = k * 256 + tid;
            float4 sum = make_float4(0.f, 0.f, 0.f, 0.f);
#pragma unroll
            for (int cc = 0; cc < CHUNKS; ++cc) {
                float4 p = *(const float4*)&base[(size_t)cc * D * DV + idx4 * 4];
                sum.x += p.x; sum.y += p.y; sum.z += p.z; sum.w += p.w;
            }
            *(float4*)&Ms[idx4 * 4] = sum;                 // keep local copy
            *(float4*)&Mb[idx4 * 4] = sum;                 // publish
        }
        __threadfence();
        __syncthreads();
        if (tid == 0) {
            *(volatile unsigned*)&g_cnt[b] = FLAG_READY;   // release flag
        }
    } else {
        if (tid == 0) {
            volatile unsigned* f = &g_cnt[b];
            while (*f != FLAG_READY) { __nanosleep(64); }
        }
        __syncthreads();
        __threadfence();  // acquire-ish before reading g_M
        const float* Mb = g_M + (size_t)b * D * DV;
#pragma unroll
        for (int k = 0; k < 16; ++k) {
            const int idx4 = k * 256 + tid;
            *(float4*)&Ms[idx4 * 4] = *(const float4*)&Mb[idx4 * 4];
        }
    }
    __syncthreads();

    // counter self-reset (last of the 16 blocks to get here resets both)
    if (tid == 0) {
        unsigned d2 = atomicAdd(&g_done[b], 1u);
        if (d2 == CHUNKS - 1) {
            *(volatile unsigned*)&g_cnt[b]  = 0u;
            *(volatile unsigned*)&g_done[b] = 0u;
        }
    }

    // ---------------- phase 2: O tile = Q tile @ M ----------------
    {
        const float* Qb = Qp + ((size_t)(b * S + c * CROWS)) * D;
        const int qrow  = tid >> 1;        // 0..127
        const int qhalf = (tid & 1) * 4;   // 0 or 4

        unsigned long long acc[4][8];
#pragma unroll
        for (int i = 0; i < 4; ++i)
#pragma unroll
            for (int j = 0; j < 8; ++j) acc[i][j] = 0ull;

        // prologue: stage 0 (d cols 0..7) stored transposed Qs[dd][row]
        {
            float4 q0 = *(const float4*)(Qb + qrow * D + qhalf);
            float qv[4] = {q0.x, q0.y, q0.z, q0.w};
#pragma unroll
            for (int k = 0; k < 4; ++k) Qs[(qhalf + k) * 128 + qrow] = qv[k];
        }
        __syncthreads();

        const int NST2 = D / 8;   // 16 stages
        for (int s = 0; s < NST2; ++s) {
            const int cur = s & 1;
            float4 qn;
            const bool more = (s + 1 < NST2);
            if (more) qn = *(const float4*)(Qb + qrow * D + (s + 1) * 8 + qhalf);

            const float* Qc = Qs + cur * 1024;
#pragma unroll
            for (int dd = 0; dd < 8; ++dd) {
                const int d = s * 8 + dd;
                float4 q4 = *(const float4*)&Qc[dd * 128 + ty * 4];
                const float* mrow = &Ms[d * DV];
                float4 m0 = *(const float4*)&mrow[tx * 16 + 0];
                float4 m1 = *(const float4*)&mrow[tx * 16 + 4];
                float4 m2f = *(const float4*)&mrow[tx * 16 + 8];
                float4 m3 = *(const float4*)&mrow[tx * 16 + 12];
                unsigned long long m2[8] = {
                    pk2(m0.x, m0.y),  pk2(m0.z, m0.w),
                    pk2(m1.x, m1.y),  pk2(m1.z, m1.w),
                    pk2(m2f.x, m2f.y), pk2(m2f.z, m2f.w),
                    pk2(m3.x, m3.y),  pk2(m3.z, m3.w) };
                float qq[4] = {q4.x, q4.y, q4.z, q4.w};
#pragma unroll
                for (int i = 0; i < 4; ++i) {
                    unsigned long long qd = pk2(qq[i], qq[i]);
#pragma unroll
                    for (int j = 0; j < 8; ++j) fma2(acc[i][j], qd, m2[j]);
                }
            }
            if (more) {
                float* Qn = Qs + (cur ^ 1) * 1024;
                float qv[4] = {qn.x, qn.y, qn.z, qn.w};
#pragma unroll
                for (int k = 0; k < 4; ++k) Qn[(qhalf + k) * 128 + qrow] = qv[k];
            }
            __syncthreads();
        }

        const float sf  = sfp[0];
        const float inv = 1.0f / (sqrtf((float)D) * sf);
        float* Ob = Op + ((size_t)(b * S + c * CROWS)) * DV;
#pragma unroll
        for (int i = 0; i < 4; ++i) {
            const int r = ty * 4 + i;
#pragma unroll
            for (int j2 = 0; j2 < 4; ++j2) {
                float2 a = unpk2(acc[i][2 * j2]);
                float2 b2 = unpk2(acc[i][2 * j2 + 1]);
                float4 w = make_float4(a.x * inv, a.y * inv,
                                       b2.x * inv, b2.y * inv);
                *(float4*)&Ob[r * DV + tx * 16 + j2 * 4] = w;
            }
        }
    }
}

// ===================== launch =====================
extern "C" void kernel_launch(void* const* d_in, const int* in_sizes, int n_in,
                              void* d_out, int out_size) {
    // metadata order: qk (unused), qk_scaling_factor, query, key, value
    const float* sf = (const float*)d_in[1];
    const float* Q  = (const float*)d_in[2];
    const float* K  = (const float*)d_in[3];
    const float* V  = (const float*)d_in[4];
    float* O        = (float*)d_out;

    const int smem_b = (D * DV + 2 * 8 * 128) * (int)sizeof(float);  // 72 KB
    cudaFuncSetAttribute(fused_attn_kernel,
                         cudaFuncAttributeMaxDynamicSharedMemorySize, smem_b);
    fused_attn_kernel<<<Bz * CHUNKS, 256, smem_b>>>(Q, K, V, sf, O);
}

// round 5
// speedup vs baseline: 4.3867x; 4.3867x over previous
#include <cuda_runtime.h>
#include <stdint.h>
#include <math.h>

// =============================== constants ===============================
namespace {
constexpr int Bz = 8, S = 2048, Dh = 128;
constexpr int CH = 16, CR = S / CH;       // 16 split-K chunks of 128 rows
constexpr int PITCHB = 272;               // smem row pitch bytes (136 bf16)
constexpr int TILE = 128 * PITCHB;        // 34816 B per 128x128 bf16 image
constexpr int SMEM_SZ = 4 * TILE;         // 139264 B
}

// =============================== scratch =================================
__device__ float    g_Mp[Bz * CH * 128 * 128];  // split-K fp32 partials (8 MB)
__device__ uint32_t g_Mh[Bz][8192];             // M hi, bf16x2 row-major [d][v]
__device__ uint32_t g_Ml[Bz][8192];             // M lo

// =============================== helpers =================================
__device__ __forceinline__ uint32_t smem_u32(const void* p) {
    uint32_t a;
    asm("{ .reg .u64 t; cvta.to.shared.u64 t, %1; cvt.u32.u64 %0, t; }"
        : "=r"(a) : "l"(p));
    return a;
}
// pack: low half = lo operand, high half = hi operand
__device__ __forceinline__ uint32_t cvt2(float hi, float lo) {
    uint32_t r;
    asm("cvt.rn.bf16x2.f32 %0, %1, %2;" : "=r"(r) : "f"(hi), "f"(lo));
    return r;
}
__device__ __forceinline__ void ldsm4(uint32_t* r, uint32_t a) {
    asm volatile("ldmatrix.sync.aligned.m8n8.x4.shared.b16 {%0,%1,%2,%3}, [%4];"
        : "=r"(r[0]), "=r"(r[1]), "=r"(r[2]), "=r"(r[3]) : "r"(a));
}
__device__ __forceinline__ void ldsm4t(uint32_t* r, uint32_t a) {
    asm volatile("ldmatrix.sync.aligned.m8n8.x4.trans.shared.b16 {%0,%1,%2,%3}, [%4];"
        : "=r"(r[0]), "=r"(r[1]), "=r"(r[2]), "=r"(r[3]) : "r"(a));
}
__device__ __forceinline__ void mma_bf16(float* d, const uint32_t* a,
                                         const uint32_t* b) {
    asm volatile(
        "mma.sync.aligned.m16n8k16.row.col.f32.bf16.bf16.f32 "
        "{%0,%1,%2,%3}, {%4,%5,%6,%7}, {%8,%9}, {%0,%1,%2,%3};"
        : "+f"(d[0]), "+f"(d[1]), "+f"(d[2]), "+f"(d[3])
        : "r"(a[0]), "r"(a[1]), "r"(a[2]), "r"(a[3]), "r"(b[0]), "r"(b[1]));
}

// fp32 [128][128] row-major gmem -> bf16 hi/lo smem images, pitch 136 bf16
__device__ __forceinline__ void load_convert(const float* __restrict__ src,
                                             char* hi, char* lo, int tid) {
    const float4* s4 = (const float4*)src;
#pragma unroll
    for (int k = 0; k < 16; ++k) {
        const int i = k * 256 + tid;
        const int r = i >> 5, c4 = (i & 31) * 4;
        float4 x = s4[i];
        uint32_t h0 = cvt2(x.y, x.x), h1 = cvt2(x.w, x.z);
        float a0 = __uint_as_float(h0 << 16);
        float a1 = __uint_as_float(h0 & 0xFFFF0000u);
        float a2 = __uint_as_float(h1 << 16);
        float a3 = __uint_as_float(h1 & 0xFFFF0000u);
        uint32_t l0 = cvt2(x.y - a1, x.x - a0);
        uint32_t l1 = cvt2(x.w - a3, x.z - a2);
        *(uint2*)(hi + r * PITCHB + c4 * 2) = make_uint2(h0, h1);
        *(uint2*)(lo + r * PITCHB + c4 * 2) = make_uint2(l0, l1);
    }
}

// core 128x128x128 split-MMA loop; A at smem off 0/TILE (hi/lo), B at
// 2*TILE/3*TILE. ATRANS: use ldmatrix.trans for A (A stored K-major).
template <bool ATRANS>
__device__ __forceinline__ void gemm_core(uint32_t sb, int lane, int wid,
                                          float acc[2][8][4]) {
    const int m_base = (wid & 3) * 32, n_base = (wid >> 2) * 64;
    uint32_t aA, bA;
    if (ATRANS) {
        // A stored [k][m]; lanes 0-7: rows k0-7 @m, 8-15: k0-7 @m+8,
        // 16-23: k8-15 @m, 24-31: k8-15 @m+8
        aA = sb + (uint32_t)((((lane & 7) + ((lane >> 4) << 3)) * PITCHB) +
                             (m_base + ((lane >> 3) & 1) * 8) * 2);
    } else {
        // A stored [m][k]; lanes 0-7: rows m0-7 @k0, 8-15: m8-15 @k0,
        // 16-23: m0-7 @k8, 24-31: m8-15 @k8
        aA = sb + (uint32_t)(((m_base + (lane & 7) + (((lane >> 3) & 1) << 3)) *
                              PITCHB) + ((lane >> 4) << 3) * 2);
    }
    // B stored [k][n]; lanes 0-7: k0-7 @n, 8-15: k8-15 @n, 16-23: k0-7 @n+8,
    // 24-31: k8-15 @n+8
    bA = sb + 2 * TILE +
         (uint32_t)((((lane & 7) + (((lane >> 3) & 1) << 3)) * PITCHB) +
                    (n_base + ((lane >> 4) << 3)) * 2);

#pragma unroll
    for (int ks = 0; ks < 8; ++ks) {
        uint32_t ah[2][4], al[2][4];
        if (ATRANS) {
            const uint32_t kb = ks * 16 * PITCHB;
            ldsm4t(ah[0], aA + kb);
            ldsm4t(ah[1], aA + kb + 32);
            ldsm4t(al[0], aA + kb + TILE);
            ldsm4t(al[1], aA + kb + TILE + 32);
        } else {
            const uint32_t kb = ks * 32;
            ldsm4(ah[0], aA + kb);
            ldsm4(ah[1], aA + kb + 16 * PITCHB);
            ldsm4(al[0], aA + kb + TILE);
            ldsm4(al[1], aA + kb + TILE + 16 * PITCHB);
        }
        const uint32_t kbB = ks * 16 * PITCHB;
#pragma unroll
        for (int h = 0; h < 2; ++h) {
            uint32_t bh[8], bl[8];
            ldsm4t(&bh[0], bA + kbB + h * 64);
            ldsm4t(&bh[4], bA + kbB + h * 64 + 32);
            ldsm4t(&bl[0], bA + kbB + TILE + h * 64);
            ldsm4t(&bl[4], bA + kbB + TILE + h * 64 + 32);
#pragma unroll
            for (int mt = 0; mt < 2; ++mt)
#pragma unroll
                for (int j = 0; j < 4; ++j) {
                    float* d = acc[mt][h * 4 + j];
                    mma_bf16(d, ah[mt], &bh[2 * j]);
                    mma_bf16(d, al[mt], &bh[2 * j]);
                    mma_bf16(d, ah[mt], &bl[2 * j]);
                }
        }
    }
}

// ========== kernel 1: split-K partial of M = K^T V for one chunk ==========
__global__ void __launch_bounds__(256, 1)
ktv_kernel(const float* __restrict__ Kp, const float* __restrict__ Vp) {
    extern __shared__ char sm[];
    const int tid = threadIdx.x, lane = tid & 31, wid = tid >> 5;
    const int b = blockIdx.x >> 4, c = blockIdx.x & 15;

    load_convert(Kp + (size_t)(b * S + c * CR) * Dh, sm, sm + TILE, tid);
    load_convert(Vp + (size_t)(b * S + c * CR) * Dh, sm + 2 * TILE,
                 sm + 3 * TILE, tid);
    __syncthreads();

    float acc[2][8][4];
#pragma unroll
    for (int i = 0; i < 2; ++i)
#pragma unroll
        for (int j = 0; j < 8; ++j)
#pragma unroll
            for (int k = 0; k < 4; ++k) acc[i][j][k] = 0.f;

    gemm_core<true>(smem_u32(sm), lane, wid, acc);   // A = K^T (trans)

    const int m_base = (wid & 3) * 32, n_base = (wid >> 2) * 64;
    const int g = lane >> 2, t = lane & 3;
    float* outp = g_Mp + ((size_t)(b * CH + c)) * 16384;
#pragma unroll
    for (int mt = 0; mt < 2; ++mt)
#pragma unroll
        for (int nt = 0; nt < 8; ++nt) {
            const int row = m_base + mt * 16 + g, col = n_base + nt * 8 + 2 * t;
            *(float2*)&outp[row * 128 + col] =
                make_float2(acc[mt][nt][0], acc[mt][nt][1]);
            *(float2*)&outp[(row + 8) * 128 + col] =
                make_float2(acc[mt][nt][2], acc[mt][nt][3]);
        }
}

// ====== kernel 2: reduce 16 partials -> M, convert to bf16 hi/lo ======
__global__ void __launch_bounds__(256, 1) reduce_kernel() {
    const int b = blockIdx.x >> 4, seg = blockIdx.x & 15;
    const int tid = threadIdx.x;
    const int d = seg * 8 + (tid >> 5), v0 = (tid & 31) * 4;
    const float* base = g_Mp + (size_t)b * CH * 16384 + d * 128 + v0;
    float4 s = make_float4(0.f, 0.f, 0.f, 0.f);
#pragma unroll
    for (int c = 0; c < CH; ++c) {
        float4 p = *(const float4*)(base + (size_t)c * 16384);
        s.x += p.x; s.y += p.y; s.z += p.z; s.w += p.w;
    }
    uint32_t h0 = cvt2(s.y, s.x), h1 = cvt2(s.w, s.z);
    float a0 = __uint_as_float(h0 << 16), a1 = __uint_as_float(h0 & 0xFFFF0000u);
    float a2 = __uint_as_float(h1 << 16), a3 = __uint_as_float(h1 & 0xFFFF0000u);
    uint32_t l0 = cvt2(s.y - a1, s.x - a0), l1 = cvt2(s.w - a3, s.z - a2);
    const int w = d * 64 + v0 / 2;   // 64 words per 128-bf16 row
    *(uint2*)&g_Mh[b][w] = make_uint2(h0, h1);
    *(uint2*)&g_Ml[b][w] = make_uint2(l0, l1);
}

// ================= kernel 3: O tile = Q tile @ M (scaled) =================
__global__ void __launch_bounds__(256, 1)
qm_kernel(const float* __restrict__ Qp, const float* __restrict__ sfp,
          float* __restrict__ Op) {
    extern __shared__ char sm[];
    const int tid = threadIdx.x, lane = tid & 31, wid = tid >> 5;
    const int b = blockIdx.x >> 4, qt = blockIdx.x & 15;

    // copy M hi/lo images into smem (re-pitch 128 -> 136 bf16)
    {
        const uint2* sh = (const uint2*)g_Mh[b];   // 4096 uint2
        const uint2* sl = (const uint2*)g_Ml[b];
        char* dh = sm + 2 * TILE;
        char* dl = sm + 3 * TILE;
#pragma unroll
        for (int k = 0; k < 16; ++k) {
            const int i = k * 256 + tid;           // 0..4095
            const int r = i >> 5, w = i & 31;      // 32 uint2 (=128 bf16)/row
            *(uint2*)(dh + r * PITCHB + w * 8) = sh[i];
            *(uint2*)(dl + r * PITCHB + w * 8) = sl[i];
        }
    }
    load_convert(Qp + (size_t)(b * S + qt * 128) * Dh, sm, sm + TILE, tid);
    __syncthreads();

    float acc[2][8][4];
#pragma unroll
    for (int i = 0; i < 2; ++i)
#pragma unroll
        for (int j = 0; j < 8; ++j)
#pragma unroll
            for (int k = 0; k < 4; ++k) acc[i][j][k] = 0.f;

    gemm_core<false>(smem_u32(sm), lane, wid, acc);  // A = Q (non-trans)

    const float inv = 1.0f / (sqrtf(128.0f) * sfp[0]);
    const int m_base = (wid & 3) * 32, n_base = (wid >> 2) * 64;
    const int g = lane >> 2, t = lane & 3;
    float* outp = Op + (size_t)(b * S + qt * 128) * 128;
#pragma unroll
    for (int mt = 0; mt < 2; ++mt)
#pragma unroll
        for (int nt = 0; nt < 8; ++nt) {
            const int row = m_base + mt * 16 + g, col = n_base + nt * 8 + 2 * t;
            *(float2*)&outp[row * 128 + col] =
                make_float2(acc[mt][nt][0] * inv, acc[mt][nt][1] * inv);
            *(float2*)&outp[(row + 8) * 128 + col] =
                make_float2(acc[mt][nt][2] * inv, acc[mt][nt][3] * inv);
        }
}

// =============================== launch ===============================
extern "C" void kernel_launch(void* const* d_in, const int* in_sizes, int n_in,
                              void* d_out, int out_size) {
    // metadata order: qk (unused), qk_scaling_factor, query, key, value
    const float* sf = (const float*)d_in[1];
    const float* Q  = (const float*)d_in[2];
    const float* K  = (const float*)d_in[3];
    const float* V  = (const float*)d_in[4];
    float* O        = (float*)d_out;

    cudaFuncSetAttribute(ktv_kernel,
                         cudaFuncAttributeMaxDynamicSharedMemorySize, SMEM_SZ);
    cudaFuncSetAttribute(qm_kernel,
                         cudaFuncAttributeMaxDynamicSharedMemorySize, SMEM_SZ);

    ktv_kernel<<<Bz * CH, 256, SMEM_SZ>>>(K, V);
    reduce_kernel<<<Bz * CH, 256>>>();
    qm_kernel<<<Bz * CH, 256, SMEM_SZ>>>(Q, sf, O);
}

// round 8
// speedup vs baseline: 4.4404x; 1.0122x over previous
#include <cuda_runtime.h>
#include <stdint.h>
#include <math.h>

// =============================== constants ===============================
namespace {
constexpr int Bz = 8, S = 2048, Dh = 128;
constexpr int CH = 16, CR = S / CH;       // 16 split-K chunks of 128 rows
constexpr int PITCHB = 272;               // smem row pitch bytes (136 bf16)
constexpr int TILE = 128 * PITCHB;        // 34816 B per 128x128 bf16 image
constexpr int SMEM_SZ = 4 * TILE;         // 139264 B
constexpr int NT = 512;                   // threads per GEMM CTA (16 warps)
}

// =============================== scratch =================================
__device__ float    g_Mp[Bz * CH * 128 * 128];  // split-K fp32 partials (8 MB)
__device__ uint32_t g_Mh[Bz][8192];             // M hi, bf16x2 row-major [d][v]
__device__ uint32_t g_Ml[Bz][8192];             // M lo

// =============================== helpers =================================
__device__ __forceinline__ uint32_t smem_u32(const void* p) {
    uint32_t a;
    asm("{ .reg .u64 t; cvta.to.shared.u64 t, %1; cvt.u32.u64 %0, t; }"
        : "=r"(a) : "l"(p));
    return a;
}
// pack: low half = lo operand, high half = hi operand
__device__ __forceinline__ uint32_t cvt2(float hi, float lo) {
    uint32_t r;
    asm("cvt.rn.bf16x2.f32 %0, %1, %2;" : "=r"(r) : "f"(hi), "f"(lo));
    return r;
}
__device__ __forceinline__ void ldsm4(uint32_t* r, uint32_t a) {
    asm volatile("ldmatrix.sync.aligned.m8n8.x4.shared.b16 {%0,%1,%2,%3}, [%4];"
        : "=r"(r[0]), "=r"(r[1]), "=r"(r[2]), "=r"(r[3]) : "r"(a));
}
__device__ __forceinline__ void ldsm4t(uint32_t* r, uint32_t a) {
    asm volatile("ldmatrix.sync.aligned.m8n8.x4.trans.shared.b16 {%0,%1,%2,%3}, [%4];"
        : "=r"(r[0]), "=r"(r[1]), "=r"(r[2]), "=r"(r[3]) : "r"(a));
}
__device__ __forceinline__ void mma_bf16(float* d, const uint32_t* a,
                                         const uint32_t* b) {
    asm volatile(
        "mma.sync.aligned.m16n8k16.row.col.f32.bf16.bf16.f32 "
        "{%0,%1,%2,%3}, {%4,%5,%6,%7}, {%8,%9}, {%0,%1,%2,%3};"
        : "+f"(d[0]), "+f"(d[1]), "+f"(d[2]), "+f"(d[3])
        : "r"(a[0]), "r"(a[1]), "r"(a[2]), "r"(a[3]), "r"(b[0]), "r"(b[1]));
}

// fp32 [128][128] row-major gmem -> bf16 hi/lo smem images, pitch 136 bf16
__device__ __forceinline__ void load_convert(const float* __restrict__ src,
                                             char* hi, char* lo, int tid) {
    const float4* s4 = (const float4*)src;
#pragma unroll
    for (int k = 0; k < 4096 / NT; ++k) {
        const int i = k * NT + tid;
        const int r = i >> 5, c4 = (i & 31) * 4;
        float4 x = s4[i];
        uint32_t h0 = cvt2(x.y, x.x), h1 = cvt2(x.w, x.z);
        float a0 = __uint_as_float(h0 << 16);
        float a1 = __uint_as_float(h0 & 0xFFFF0000u);
        float a2 = __uint_as_float(h1 << 16);
        float a3 = __uint_as_float(h1 & 0xFFFF0000u);
        uint32_t l0 = cvt2(x.y - a1, x.x - a0);
        uint32_t l1 = cvt2(x.w - a3, x.z - a2);
        *(uint2*)(hi + r * PITCHB + c4 * 2) = make_uint2(h0, h1);
        *(uint2*)(lo + r * PITCHB + c4 * 2) = make_uint2(l0, l1);
    }
}

// core 128x128x128 split-MMA; 16 warps, warp tile 32x32.
// A at smem off 0/TILE (hi/lo), B at 2*TILE/3*TILE.
// ATRANS: use ldmatrix.trans for A (A stored K-major).
template <bool ATRANS>
__device__ __forceinline__ void gemm_core(uint32_t sb, int lane, int wid,
                                          float acc[2][4][4]) {
    const int m_base = (wid & 3) * 32, n_base = (wid >> 2) * 32;
    uint32_t aA, bA;
    if (ATRANS) {
        // A stored [k][m]; lanes 0-7: k0-7 @m, 8-15: k0-7 @m+8,
        // 16-23: k8-15 @m, 24-31: k8-15 @m+8
        aA = sb + (uint32_t)((((lane & 7) + ((lane >> 4) << 3)) * PITCHB) +
                             (m_base + ((lane >> 3) & 1) * 8) * 2);
    } else {
        // A stored [m][k]; lanes 0-7: m0-7 @k0, 8-15: m8-15 @k0,
        // 16-23: m0-7 @k8, 24-31: m8-15 @k8
        aA = sb + (uint32_t)(((m_base + (lane & 7) + (((lane >> 3) & 1) << 3)) *
                              PITCHB) + ((lane >> 4) << 3) * 2);
    }
    // B stored [k][n]; lanes 0-7: k0-7 @n, 8-15: k8-15 @n, 16-23: k0-7 @n+8,
    // 24-31: k8-15 @n+8
    bA = sb + 2 * TILE +
         (uint32_t)((((lane & 7) + (((lane >> 3) & 1) << 3)) * PITCHB) +
                    (n_base + ((lane >> 4) << 3)) * 2);

#pragma unroll
    for (int ks = 0; ks < 8; ++ks) {
        uint32_t ah[2][4], al[2][4];
        if (ATRANS) {
            const uint32_t kb = ks * 16 * PITCHB;
            ldsm4t(ah[0], aA + kb);
            ldsm4t(ah[1], aA + kb + 32);
            ldsm4t(al[0], aA + kb + TILE);
            ldsm4t(al[1], aA + kb + TILE + 32);
        } else {
            const uint32_t kb = ks * 32;
            ldsm4(ah[0], aA + kb);
            ldsm4(ah[1], aA + kb + 16 * PITCHB);
            ldsm4(al[0], aA + kb + TILE);
            ldsm4(al[1], aA + kb + TILE + 16 * PITCHB);
        }
        const uint32_t kbB = ks * 16 * PITCHB;
        uint32_t bh[8], bl[8];
        ldsm4t(&bh[0], bA + kbB);
        ldsm4t(&bh[4], bA + kbB + 32);
        ldsm4t(&bl[0], bA + kbB + TILE);
        ldsm4t(&bl[4], bA + kbB + TILE + 32);
#pragma unroll
        for (int mt = 0; mt < 2; ++mt)
#pragma unroll
            for (int j = 0; j < 4; ++j) {
                float* d = acc[mt][j];
                mma_bf16(d, ah[mt], &bh[2 * j]);
                mma_bf16(d, al[mt], &bh[2 * j]);
                mma_bf16(d, ah[mt], &bl[2 * j]);
            }
    }
}

// ========== kernel 1: split-K partial of M = K^T V for one chunk ==========
__global__ void __launch_bounds__(NT, 1)
ktv_kernel(const float* __restrict__ Kp, const float* __restrict__ Vp) {
    extern __shared__ char sm[];
    const int tid = threadIdx.x, lane = tid & 31, wid = tid >> 5;
    const int b = blockIdx.x >> 4, c = blockIdx.x & 15;

    load_convert(Kp + (size_t)(b * S + c * CR) * Dh, sm, sm + TILE, tid);
    load_convert(Vp + (size_t)(b * S + c * CR) * Dh, sm + 2 * TILE,
                 sm + 3 * TILE, tid);
    __syncthreads();

    float acc[2][4][4];
#pragma unroll
    for (int i = 0; i < 2; ++i)
#pragma unroll
        for (int j = 0; j < 4; ++j)
#pragma unroll
            for (int k = 0; k < 4; ++k) acc[i][j][k] = 0.f;

    gemm_core<true>(smem_u32(sm), lane, wid, acc);   // A = K^T (trans)

    const int m_base = (wid & 3) * 32, n_base = (wid >> 2) * 32;
    const int g = lane >> 2, t = lane & 3;
    float* outp = g_Mp + ((size_t)(b * CH + c)) * 16384;
#pragma unroll
    for (int mt = 0; mt < 2; ++mt)
#pragma unroll
        for (int nt = 0; nt < 4; ++nt) {
            const int row = m_base + mt * 16 + g, col = n_base + nt * 8 + 2 * t;
            *(float2*)&outp[row * 128 + col] =
                make_float2(acc[mt][nt][0], acc[mt][nt][1]);
            *(float2*)&outp[(row + 8) * 128 + col] =
                make_float2(acc[mt][nt][2], acc[mt][nt][3]);
        }
}

// ====== kernel 2: reduce 16 partials -> M, convert to bf16 hi/lo ======
__global__ void __launch_bounds__(256, 1) reduce_kernel() {
    const int b = blockIdx.x >> 4, seg = blockIdx.x & 15;
    const int tid = threadIdx.x;
    const int d = seg * 8 + (tid >> 5), v0 = (tid & 31) * 4;
    const float* base = g_Mp + (size_t)b * CH * 16384 + d * 128 + v0;
    float4 s = make_float4(0.f, 0.f, 0.f, 0.f);
#pragma unroll
    for (int c = 0; c < CH; ++c) {
        float4 p = *(const float4*)(base + (size_t)c * 16384);
        s.x += p.x; s.y += p.y; s.z += p.z; s.w += p.w;
    }
    uint32_t h0 = cvt2(s.y, s.x), h1 = cvt2(s.w, s.z);
    float a0 = __uint_as_float(h0 << 16), a1 = __uint_as_float(h0 & 0xFFFF0000u);
    float a2 = __uint_as_float(h1 << 16), a3 = __uint_as_float(h1 & 0xFFFF0000u);
    uint32_t l0 = cvt2(s.y - a1, s.x - a0), l1 = cvt2(s.w - a3, s.z - a2);
    const int w = d * 64 + v0 / 2;   // 64 words per 128-bf16 row
    *(uint2*)&g_Mh[b][w] = make_uint2(h0, h1);
    *(uint2*)&g_Ml[b][w] = make_uint2(l0, l1);
}

// ================= kernel 3: O tile = Q tile @ M (scaled) =================
__global__ void __launch_bounds__(NT, 1)
qm_kernel(const float* __restrict__ Qp, const float* __restrict__ sfp,
          float* __restrict__ Op) {
    extern __shared__ char sm[];
    const int tid = threadIdx.x, lane = tid & 31, wid = tid >> 5;
    const int b = blockIdx.x >> 4, qt = blockIdx.x & 15;

    // copy M hi/lo images into smem (re-pitch 128 -> 136 bf16)
    {
        const uint2* sh = (const uint2*)g_Mh[b];   // 4096 uint2
        const uint2* sl = (const uint2*)g_Ml[b];
        char* dh = sm + 2 * TILE;
        char* dl = sm + 3 * TILE;
#pragma unroll
        for (int k = 0; k < 4096 / NT; ++k) {
            const int i = k * NT + tid;            // 0..4095
            const int r = i >> 5, w = i & 31;      // 32 uint2 (=128 bf16)/row
            *(uint2*)(dh + r * PITCHB + w * 8) = sh[i];
            *(uint2*)(dl + r * PITCHB + w * 8) = sl[i];
        }
    }
    load_convert(Qp + (size_t)(b * S + qt * 128) * Dh, sm, sm + TILE, tid);
    __syncthreads();

    float acc[2][4][4];
#pragma unroll
    for (int i = 0; i < 2; ++i)
#pragma unroll
        for (int j = 0; j < 4; ++j)
#pragma unroll
            for (int k = 0; k < 4; ++k) acc[i][j][k] = 0.f;

    gemm_core<false>(smem_u32(sm), lane, wid, acc);  // A = Q (non-trans)

    const float inv = 1.0f / (sqrtf(128.0f) * sfp[0]);
    const int m_base = (wid & 3) * 32, n_base = (wid >> 2) * 32;
    const int g = lane >> 2, t = lane & 3;
    float* outp = Op + (size_t)(b * S + qt * 128) * 128;
#pragma unroll
    for (int mt = 0; mt < 2; ++mt)
#pragma unroll
        for (int nt = 0; nt < 4; ++nt) {
            const int row = m_base + mt * 16 + g, col = n_base + nt * 8 + 2 * t;
            *(float2*)&outp[row * 128 + col] =
                make_float2(acc[mt][nt][0] * inv, acc[mt][nt][1] * inv);
            *(float2*)&outp[(row + 8) * 128 + col] =
                make_float2(acc[mt][nt][2] * inv, acc[mt][nt][3] * inv);
        }
}

// =============================== launch ===============================
extern "C" void kernel_launch(void* const* d_in, const int* in_sizes, int n_in,
                              void* d_out, int out_size) {
    // metadata order: qk (unused), qk_scaling_factor, query, key, value
    const float* sf = (const float*)d_in[1];
    const float* Q  = (const float*)d_in[2];
    const float* K  = (const float*)d_in[3];
    const float* V  = (const float*)d_in[4];
    float* O        = (float*)d_out;

    cudaFuncSetAttribute(ktv_kernel,
                         cudaFuncAttributeMaxDynamicSharedMemorySize, SMEM_SZ);
    cudaFuncSetAttribute(qm_kernel,
                         cudaFuncAttributeMaxDynamicSharedMemorySize, SMEM_SZ);

    ktv_kernel<<<Bz * CH, NT, SMEM_SZ>>>(K, V);
    reduce_kernel<<<Bz * CH, 256>>>();
    qm_kernel<<<Bz * CH, NT, SMEM_SZ>>>(Q, sf, O);
}